// round 1
// baseline (speedup 1.0000x reference)
#include <cuda_runtime.h>
#include <stdint.h>

#define NATOMS 4096
#define DD     352     // 128 + 128 + 96
#define H      256
#define SEL    128
#define ASEL   16

// ---------------- scratch (no allocations allowed) ----------------
__device__ int   g_cnt[2];
__device__ int   g_list[2 * NATOMS];
__device__ float g_desc[(size_t)NATOMS * DD];
__device__ float g_energy[NATOMS];

// ---------------- helpers ----------------
__device__ __forceinline__ float key_dist(unsigned long long k) {
    return __uint_as_float((unsigned)((k >> 12) & 0x7FFFFFFFull));
}
__device__ __forceinline__ int key_idx(unsigned long long k) {
    return (int)(k & 0xFFFull);
}

// wrapped displacement, replicating reference: d = xi - xj + 1e-16; d -= box*round(d/box)
__device__ __forceinline__ void dm_vec(float xi, float yi, float zi,
                                       const float* __restrict__ xyz, int j,
                                       float bx, float by, float bz,
                                       float& dx, float& dy, float& dz) {
    dx = xi - xyz[3 * j + 0] + 1e-16f;
    dy = yi - xyz[3 * j + 1] + 1e-16f;
    dz = zi - xyz[3 * j + 2] + 1e-16f;
    dx -= bx * rintf(dx / bx);
    dy -= by * rintf(dy / by);
    dz -= bz * rintf(dz / bz);
}

// ---------------- kernels ----------------
__global__ void k_init() { g_cnt[0] = 0; g_cnt[1] = 0; }

__global__ void k_lists(const int* __restrict__ types) {
    int i = blockIdx.x * blockDim.x + threadIdx.x;
    if (i < NATOMS) {
        int t = types[i];
        int p = atomicAdd(&g_cnt[t], 1);
        g_list[t * NATOMS + p] = i;
    }
}

// One block per atom. Distances to all atoms, fused-key bitonic sort
// (type-major, then distance, then index), then descriptor assembly.
__global__ void __launch_bounds__(256) k_desc(const float* __restrict__ xyz,
                                              const float* __restrict__ box,
                                              const int* __restrict__ types) {
    __shared__ unsigned long long keys[NATOMS];
    __shared__ float sA[9];   // local frame rows r0, v2, v3
    __shared__ int   s_c0;

    const int i   = blockIdx.x;
    const int tid = threadIdx.x;
    const float bx = box[0], by = box[1], bz = box[2];
    const float xi = xyz[3 * i], yi = xyz[3 * i + 1], zi = xyz[3 * i + 2];

    // distance + key build
    for (int j = tid; j < NATOMS; j += 256) {
        float dx, dy, dz;
        dm_vec(xi, yi, zi, xyz, j, bx, by, bz, dx, dy, dz);
        float d = sqrtf(dx * dx + dy * dy + dz * dz);
        unsigned bits = __float_as_uint(d);
        if (j == i) bits = 0x7f800000u;          // self -> +inf, stays inside its type segment
        keys[j] = ((unsigned long long)types[j] << 43)
                | ((unsigned long long)bits << 12)
                | (unsigned)j;
    }
    if (tid == 0) s_c0 = g_cnt[0];
    __syncthreads();

    // bitonic sort ascending (4096 elems, 256 threads)
    for (int k = 2; k <= NATOMS; k <<= 1) {
        for (int jj = k >> 1; jj > 0; jj >>= 1) {
            for (int idx = tid; idx < NATOMS; idx += 256) {
                int l = idx ^ jj;
                if (l > idx) {
                    unsigned long long a = keys[idx], b = keys[l];
                    bool up = ((idx & k) == 0);
                    if ((a > b) == up) { keys[idx] = b; keys[l] = a; }
                }
            }
            __syncthreads();
        }
    }

    const int c0 = s_c0;                 // type-0 segment length
    float* dsc = g_desc + (size_t)i * DD;

    // radial blocks: 1/(d + eps)
    if (tid < SEL) {
        dsc[tid] = 1.0f / (key_dist(keys[tid]) + 1e-16f);
    } else {
        int s = tid - SEL;               // tid in [128,256)
        dsc[SEL + s] = 1.0f / (key_dist(keys[c0 + s]) + 1e-16f);
    }

    // local frame (thread 0): stable merge of two nearest of each type
    if (tid == 0) {
        float d00 = key_dist(keys[0]),      d01 = key_dist(keys[1]);
        float d10 = key_dist(keys[c0]),     d11 = key_dist(keys[c0 + 1]);
        int   i00 = key_idx(keys[0]),       i01 = key_idx(keys[1]);
        int   i10 = key_idx(keys[c0]),      i11 = key_idx(keys[c0 + 1]);

        float lfd0, lfd1; int lfi0, lfi1;
        if (d10 < d00) {                       // first = type-1 nearest
            lfd0 = d10; lfi0 = i10;
            if (d11 < d00) { lfd1 = d11; lfi1 = i11; }
            else           { lfd1 = d00; lfi1 = i00; }
        } else {                               // first = type-0 nearest
            lfd0 = d00; lfi0 = i00;
            if (d10 < d01) { lfd1 = d10; lfi1 = i10; }
            else           { lfd1 = d01; lfi1 = i01; }
        }

        float ax, ay, az, bx2, by2, bz2;
        dm_vec(xi, yi, zi, xyz, lfi0, bx, by, bz, ax, ay, az);
        dm_vec(xi, yi, zi, xyz, lfi1, bx, by, bz, bx2, by2, bz2);
        float inv0 = 1.0f / (lfd0 + 1e-16f);
        float inv1 = 1.0f / (lfd1 + 1e-16f);
        float r0x = ax * inv0,  r0y = ay * inv0,  r0z = az * inv0;
        float r1x = bx2 * inv1, r1y = by2 * inv1, r1z = bz2 * inv1;

        float dot = r0x * r1x + r0y * r1y + r0z * r1z;
        float v2x = r1x - dot * r0x, v2y = r1y - dot * r0y, v2z = r1z - dot * r0z;
        float n2 = sqrtf(v2x * v2x + v2y * v2y + v2z * v2z);
        v2x /= n2; v2y /= n2; v2z /= n2;
        float v3x = r0y * r1z - r0z * r1y;
        float v3y = r0z * r1x - r0x * r1z;
        float v3z = r0x * r1y - r0y * r1x;
        float n3 = sqrtf(v3x * v3x + v3y * v3y + v3z * v3z);
        v3x /= n3; v3y /= n3; v3z /= n3;

        sA[0] = r0x; sA[1] = r0y; sA[2] = r0z;
        sA[3] = v2x; sA[4] = v2y; sA[5] = v2z;
        sA[6] = v3x; sA[7] = v3y; sA[8] = v3z;
    }
    __syncthreads();

    // angular block: rot[k][r] = (A_r . dm_k) / (d_k+eps)^2
    if (tid < 2 * ASEL) {
        int k = tid;
        unsigned long long key = (k < ASEL) ? keys[k] : keys[c0 + (k - ASEL)];
        float ad = key_dist(key);
        int   j  = key_idx(key);
        float vx, vy, vz;
        dm_vec(xi, yi, zi, xyz, j, bx, by, bz, vx, vy, vz);
        float inv = 1.0f / (ad + 1e-16f);
        // a_n = dm*inv, rot = (A . a_n)*inv
        float nx = vx * inv, ny = vy * inv, nz = vz * inv;
        #pragma unroll
        for (int r = 0; r < 3; r++) {
            float val = (sA[3 * r + 0] * nx + sA[3 * r + 1] * ny + sA[3 * r + 2] * nz) * inv;
            dsc[2 * SEL + k * 3 + r] = val;
        }
    }
}

// 16 atoms (same type) per block, 256 threads = 256 output neurons.
__global__ void __launch_bounds__(256) k_mlp(const float* __restrict__ w1, const float* __restrict__ b1,
                                             const float* __restrict__ w2, const float* __restrict__ b2,
                                             const float* __restrict__ w3, const float* __restrict__ b3,
                                             const float* __restrict__ w4, const float* __restrict__ b4) {
    __shared__ float bufA[16 * DD];   // 5632 floats
    __shared__ float bufB[16 * H];    // 4096 floats

    const int b    = blockIdx.x;
    const int t    = b >> 8;          // 256 tiles per type
    const int tile = b & 255;
    const int cnt  = g_cnt[t];
    const int base = tile * 16;
    if (base >= cnt) return;
    const int na  = min(16, cnt - base);
    const int tid = threadIdx.x;

    // load descriptors for this tile; zero unused rows
    for (int a = 0; a < na; a++) {
        int gi = g_list[t * NATOMS + base + a];
        const float* src = g_desc + (size_t)gi * DD;
        for (int d = tid; d < DD; d += 256) bufA[a * DD + d] = src[d];
    }
    for (int a = na; a < 16; a++)
        for (int d = tid; d < DD; d += 256) bufA[a * DD + d] = 0.0f;
    __syncthreads();

    float acc[16];

    // ---- layer 1: DD -> H (bufA -> bufB)
    {
        const float* W = w1 + (size_t)t * DD * H;
        #pragma unroll
        for (int a = 0; a < 16; a++) acc[a] = 0.0f;
        for (int d = 0; d < DD; d++) {
            float w = W[d * H + tid];
            #pragma unroll
            for (int a = 0; a < 16; a++) acc[a] = fmaf(bufA[a * DD + d], w, acc[a]);
        }
        float bb = b1[t * H + tid];
        __syncthreads();
        #pragma unroll
        for (int a = 0; a < 16; a++) bufB[a * H + tid] = tanhf(acc[a] + bb);
        __syncthreads();
    }

    // ---- layer 2: H -> H (bufB -> bufA)
    {
        const float* W = w2 + (size_t)t * H * H;
        #pragma unroll
        for (int a = 0; a < 16; a++) acc[a] = 0.0f;
        for (int d = 0; d < H; d++) {
            float w = W[d * H + tid];
            #pragma unroll
            for (int a = 0; a < 16; a++) acc[a] = fmaf(bufB[a * H + d], w, acc[a]);
        }
        float bb = b2[t * H + tid];
        __syncthreads();
        #pragma unroll
        for (int a = 0; a < 16; a++) bufA[a * H + tid] = tanhf(acc[a] + bb);
        __syncthreads();
    }

    // ---- layer 3: H -> H (bufA -> bufB)
    {
        const float* W = w3 + (size_t)t * H * H;
        #pragma unroll
        for (int a = 0; a < 16; a++) acc[a] = 0.0f;
        for (int d = 0; d < H; d++) {
            float w = W[d * H + tid];
            #pragma unroll
            for (int a = 0; a < 16; a++) acc[a] = fmaf(bufA[a * H + d], w, acc[a]);
        }
        float bb = b3[t * H + tid];
        __syncthreads();
        #pragma unroll
        for (int a = 0; a < 16; a++) bufB[a * H + tid] = tanhf(acc[a] + bb);
        __syncthreads();
    }

    // ---- layer 4: H -> 1, per-atom warp reduction
    {
        int lane = tid & 31, wrp = tid >> 5;          // 8 warps
        for (int a = wrp; a < na; a += 8) {
            float s = 0.0f;
            for (int f = lane; f < H; f += 32)
                s += bufB[a * H + f] * w4[t * H + f];
            #pragma unroll
            for (int o = 16; o; o >>= 1) s += __shfl_down_sync(0xFFFFFFFFu, s, o);
            if (lane == 0) {
                int gi = g_list[t * NATOMS + base + a];
                g_energy[gi] = s + b4[t];
            }
        }
    }
}

__global__ void k_reduce(float* __restrict__ out) {
    __shared__ float sh[256];
    float s = 0.0f;
    for (int i = threadIdx.x; i < NATOMS; i += 256) s += g_energy[i];
    sh[threadIdx.x] = s;
    __syncthreads();
    for (int o = 128; o; o >>= 1) {
        if (threadIdx.x < o) sh[threadIdx.x] += sh[threadIdx.x + o];
        __syncthreads();
    }
    if (threadIdx.x == 0) out[0] = sh[0];
}

// ---------------- launch ----------------
extern "C" void kernel_launch(void* const* d_in, const int* in_sizes, int n_in,
                              void* d_out, int out_size) {
    const float* xyz   = (const float*)d_in[0];
    const float* box   = (const float*)d_in[1];
    const int*   types = (const int*)  d_in[2];
    const float* w1 = (const float*)d_in[3];
    const float* b1 = (const float*)d_in[4];
    const float* w2 = (const float*)d_in[5];
    const float* b2 = (const float*)d_in[6];
    const float* w3 = (const float*)d_in[7];
    const float* b3 = (const float*)d_in[8];
    const float* w4 = (const float*)d_in[9];
    const float* b4 = (const float*)d_in[10];

    k_init  <<<1, 1>>>();
    k_lists <<<NATOMS / 256, 256>>>(types);
    k_desc  <<<NATOMS, 256>>>(xyz, box, types);
    k_mlp   <<<512, 256>>>(w1, b1, w2, b2, w3, b3, w4, b4);
    k_reduce<<<1, 256>>>((float*)d_out);
}

// round 2
// speedup vs baseline: 5.6158x; 5.6158x over previous
#include <cuda_runtime.h>
#include <stdint.h>

#define NATOMS 4096
#define DD     352     // 128 + 128 + 96
#define H      256
#define SEL    128
#define ASEL   16
#define NBIN   256
#define CAP    256     // candidate capacity per type (expected ~135)

// ---------------- scratch (no allocations allowed) ----------------
__device__ int   g_cnt[2];
__device__ int   g_list[2 * NATOMS];
__device__ float g_desc[(size_t)NATOMS * DD];
__device__ float g_energy[NATOMS];

// ---------------- helpers ----------------
__device__ __forceinline__ float key_dist(unsigned long long k) {
    return __uint_as_float((unsigned)((k >> 12) & 0x7FFFFFFFull));
}
__device__ __forceinline__ int key_idx(unsigned long long k) {
    return (int)(k & 0xFFFull);
}

// wrapped displacement: d = xi - xj + 1e-16; d -= box*round(d/box)  (recip form)
__device__ __forceinline__ void dm_vec(float xi, float yi, float zi,
                                       const float* __restrict__ xyz, int j,
                                       float bx, float by, float bz,
                                       float ibx, float iby, float ibz,
                                       float& dx, float& dy, float& dz) {
    dx = xi - xyz[3 * j + 0] + 1e-16f;
    dy = yi - xyz[3 * j + 1] + 1e-16f;
    dz = zi - xyz[3 * j + 2] + 1e-16f;
    dx -= bx * rintf(dx * ibx);
    dy -= by * rintf(dy * iby);
    dz -= bz * rintf(dz * ibz);
}

// ---------------- kernels ----------------
__global__ void k_init() { g_cnt[0] = 0; g_cnt[1] = 0; }

__global__ void k_lists(const int* __restrict__ types) {
    int i = blockIdx.x * blockDim.x + threadIdx.x;
    if (i < NATOMS) {
        int t = types[i];
        int p = atomicAdd(&g_cnt[t], 1);
        g_list[t * NATOMS + p] = i;
    }
}

// One block per atom. Histogram-threshold neighbor selection + small sort.
__global__ void __launch_bounds__(256) k_desc(const float* __restrict__ xyz,
                                              const float* __restrict__ box,
                                              const int* __restrict__ types) {
    __shared__ unsigned           sdist[NATOMS];      // dist bits | type<<31   (16KB)
    __shared__ int                hist[2][NBIN];      // per-type histogram     (2KB)
    __shared__ unsigned long long cand[2 * CAP];      // candidates             (4KB)
    __shared__ int                s_cut[2], s_cnt[2];
    __shared__ float              sA[9];

    const int i   = blockIdx.x;
    const int tid = threadIdx.x;
    const int lane = tid & 31, wrp = tid >> 5;
    const float bx = box[0], by = box[1], bz = box[2];
    const float ibx = 1.0f / bx, iby = 1.0f / by, ibz = 1.0f / bz;
    const float xi = xyz[3 * i], yi = xyz[3 * i + 1], zi = xyz[3 * i + 2];
    const float BIN_SCALE = (float)NBIN / 35.0f;      // max wrapped dist = 20*sqrt(3) < 35

    // zero histogram, init candidates/counters
    hist[0][tid] = 0;
    hist[1][tid] = 0;
    cand[tid]       = ~0ull;
    cand[tid + 256] = ~0ull;
    if (tid < 2) s_cnt[tid] = 0;
    __syncthreads();

    // Pass A: distances, store bits+type, histogram
    for (int j = tid; j < NATOMS; j += 256) {
        float dx, dy, dz;
        dm_vec(xi, yi, zi, xyz, j, bx, by, bz, ibx, iby, ibz, dx, dy, dz);
        float d = sqrtf(dx * dx + dy * dy + dz * dz);
        int t = types[j];
        unsigned bits;
        if (j == i) {
            bits = 0x7f800000u;                        // self -> +inf (never selected)
        } else {
            bits = __float_as_uint(d);
            int b = min((int)(d * BIN_SCALE), NBIN - 1);
            atomicAdd(&hist[t][b], 1);
        }
        sdist[j] = bits | ((unsigned)t << 31);
    }
    __syncthreads();

    // Scan: warp 0 -> type 0, warp 1 -> type 1. Find first bin where cumsum >= SEL.
    if (wrp < 2) {
        int t = wrp;
        int carry = 0, cut = NBIN - 1;
        #pragma unroll
        for (int c = 0; c < NBIN / 32; c++) {
            int b = c * 32 + lane;
            int v = hist[t][b];
            int orig = v;
            #pragma unroll
            for (int o = 1; o < 32; o <<= 1) {
                int n = __shfl_up_sync(0xFFFFFFFFu, v, o);
                if (lane >= o) v += n;
            }
            v += carry;
            int prev = v - orig;                       // exclusive cumsum
            if (prev < SEL && v >= SEL) cut = b;
            carry = __shfl_sync(0xFFFFFFFFu, v, 31);
        }
        #pragma unroll
        for (int o = 16; o; o >>= 1) cut = min(cut, __shfl_xor_sync(0xFFFFFFFFu, cut, o));
        if (lane == 0) s_cut[t] = cut;
    }
    __syncthreads();

    // Pass B: collect candidates in bins <= cutoff
    const int cut0 = s_cut[0], cut1 = s_cut[1];
    for (int j = tid; j < NATOMS; j += 256) {
        unsigned sv = sdist[j];
        int t = (int)(sv >> 31);
        unsigned bits = sv & 0x7FFFFFFFu;
        int b = min((int)(__uint_as_float(bits) * BIN_SCALE), NBIN - 1);
        if (b <= (t ? cut1 : cut0)) {
            int pos = atomicAdd(&s_cnt[t], 1);
            if (pos < CAP)
                cand[t * CAP + pos] = ((unsigned long long)bits << 12) | (unsigned)j;
        }
    }
    __syncthreads();

    // Bitonic sort: two independent 256-element arrays; 128 threads each.
    {
        const int arr  = tid >> 7;                     // 0 or 1
        const int t128 = tid & 127;
        unsigned long long* base = cand + arr * CAP;
        for (int k = 2; k <= CAP; k <<= 1) {
            for (int j = k >> 1; j > 0; j >>= 1) {
                int i1 = ((t128 & ~(j - 1)) << 1) | (t128 & (j - 1));
                int i2 = i1 | j;
                unsigned long long a = base[i1], b = base[i2];
                bool up = ((i1 & k) == 0);
                if ((a > b) == up) { base[i1] = b; base[i2] = a; }
                __syncthreads();
            }
        }
    }

    float* dsc = g_desc + (size_t)i * DD;

    // radial blocks: 1/(d + eps)
    if (tid < SEL) {
        dsc[tid] = 1.0f / (key_dist(cand[tid]) + 1e-16f);
    } else {
        int s = tid - SEL;
        dsc[SEL + s] = 1.0f / (key_dist(cand[CAP + s]) + 1e-16f);
    }

    // local frame (thread 0): stable merge of two nearest of each type
    if (tid == 0) {
        float d00 = key_dist(cand[0]),       d01 = key_dist(cand[1]);
        float d10 = key_dist(cand[CAP]),     d11 = key_dist(cand[CAP + 1]);
        int   i00 = key_idx(cand[0]),        i01 = key_idx(cand[1]);
        int   i10 = key_idx(cand[CAP]),      i11 = key_idx(cand[CAP + 1]);

        float lfd0, lfd1; int lfi0, lfi1;
        if (d10 < d00) {
            lfd0 = d10; lfi0 = i10;
            if (d11 < d00) { lfd1 = d11; lfi1 = i11; }
            else           { lfd1 = d00; lfi1 = i00; }
        } else {
            lfd0 = d00; lfi0 = i00;
            if (d10 < d01) { lfd1 = d10; lfi1 = i10; }
            else           { lfd1 = d01; lfi1 = i01; }
        }

        float ax, ay, az, bx2, by2, bz2;
        dm_vec(xi, yi, zi, xyz, lfi0, bx, by, bz, ibx, iby, ibz, ax, ay, az);
        dm_vec(xi, yi, zi, xyz, lfi1, bx, by, bz, ibx, iby, ibz, bx2, by2, bz2);
        float inv0 = 1.0f / (lfd0 + 1e-16f);
        float inv1 = 1.0f / (lfd1 + 1e-16f);
        float r0x = ax * inv0,  r0y = ay * inv0,  r0z = az * inv0;
        float r1x = bx2 * inv1, r1y = by2 * inv1, r1z = bz2 * inv1;

        float dot = r0x * r1x + r0y * r1y + r0z * r1z;
        float v2x = r1x - dot * r0x, v2y = r1y - dot * r0y, v2z = r1z - dot * r0z;
        float n2 = sqrtf(v2x * v2x + v2y * v2y + v2z * v2z);
        v2x /= n2; v2y /= n2; v2z /= n2;
        float v3x = r0y * r1z - r0z * r1y;
        float v3y = r0z * r1x - r0x * r1z;
        float v3z = r0x * r1y - r0y * r1x;
        float n3 = sqrtf(v3x * v3x + v3y * v3y + v3z * v3z);
        v3x /= n3; v3y /= n3; v3z /= n3;

        sA[0] = r0x; sA[1] = r0y; sA[2] = r0z;
        sA[3] = v2x; sA[4] = v2y; sA[5] = v2z;
        sA[6] = v3x; sA[7] = v3y; sA[8] = v3z;
    }
    __syncthreads();

    // angular block: rot[k][r] = (A_r . dm_k) / (d_k+eps)^2
    if (tid < 2 * ASEL) {
        int k = tid;
        unsigned long long key = (k < ASEL) ? cand[k] : cand[CAP + (k - ASEL)];
        float ad = key_dist(key);
        int   j  = key_idx(key);
        float vx, vy, vz;
        dm_vec(xi, yi, zi, xyz, j, bx, by, bz, ibx, iby, ibz, vx, vy, vz);
        float inv = 1.0f / (ad + 1e-16f);
        float nx = vx * inv, ny = vy * inv, nz = vz * inv;
        #pragma unroll
        for (int r = 0; r < 3; r++) {
            float val = (sA[3 * r + 0] * nx + sA[3 * r + 1] * ny + sA[3 * r + 2] * nz) * inv;
            dsc[2 * SEL + k * 3 + r] = val;
        }
    }
}

// ---------------- MLP ----------------
// one layer: DIM inputs -> 256 outputs, 16 atoms, 256 threads (thread = neuron)
template<int DIM>
__device__ __forceinline__ void mlp_layer(const float* __restrict__ W,
                                          const float* __restrict__ B,
                                          const float* in, float* out,
                                          int t, int tid, bool act) {
    float acc[16];
    #pragma unroll
    for (int a = 0; a < 16; a++) acc[a] = 0.0f;
    const float* Wp = W + (size_t)t * DIM * H + tid;
    for (int d = 0; d < DIM; d += 8) {
        float w0 = Wp[(d + 0) * H];
        float w1 = Wp[(d + 1) * H];
        float w2 = Wp[(d + 2) * H];
        float w3 = Wp[(d + 3) * H];
        float w4v = Wp[(d + 4) * H];
        float w5 = Wp[(d + 5) * H];
        float w6 = Wp[(d + 6) * H];
        float w7 = Wp[(d + 7) * H];
        #pragma unroll
        for (int a = 0; a < 16; a++) {
            const float4 x0 = *(const float4*)(in + a * DIM + d);
            const float4 x1 = *(const float4*)(in + a * DIM + d + 4);
            float s = acc[a];
            s = fmaf(x0.x, w0, s);
            s = fmaf(x0.y, w1, s);
            s = fmaf(x0.z, w2, s);
            s = fmaf(x0.w, w3, s);
            s = fmaf(x1.x, w4v, s);
            s = fmaf(x1.y, w5, s);
            s = fmaf(x1.z, w6, s);
            s = fmaf(x1.w, w7, s);
            acc[a] = s;
        }
    }
    float bb = B[t * H + tid];
    #pragma unroll
    for (int a = 0; a < 16; a++) {
        float v = acc[a] + bb;
        out[a * H + tid] = act ? tanhf(v) : v;
    }
    __syncthreads();
}

// 16 atoms (same type) per block, 256 threads = 256 output neurons.
__global__ void __launch_bounds__(256) k_mlp(const float* __restrict__ w1, const float* __restrict__ b1,
                                             const float* __restrict__ w2, const float* __restrict__ b2,
                                             const float* __restrict__ w3, const float* __restrict__ b3,
                                             const float* __restrict__ w4, const float* __restrict__ b4) {
    __shared__ float bufA[16 * DD];   // 5632 floats (22.5 KB)
    __shared__ float bufB[16 * H];    // 4096 floats (16 KB)

    const int b    = blockIdx.x;
    const int t    = b >> 8;
    const int tile = b & 255;
    const int cnt  = g_cnt[t];
    const int base = tile * 16;
    if (base >= cnt) return;
    const int na  = min(16, cnt - base);
    const int tid = threadIdx.x;

    for (int a = 0; a < na; a++) {
        int gi = g_list[t * NATOMS + base + a];
        const float* src = g_desc + (size_t)gi * DD;
        for (int d = tid; d < DD; d += 256) bufA[a * DD + d] = src[d];
    }
    for (int a = na; a < 16; a++)
        for (int d = tid; d < DD; d += 256) bufA[a * DD + d] = 0.0f;
    __syncthreads();

    mlp_layer<DD>(w1, b1, bufA, bufB, t, tid, true);   // L1: 352 -> 256
    mlp_layer<H >(w2, b2, bufB, bufA, t, tid, true);   // L2: 256 -> 256
    mlp_layer<H >(w3, b3, bufA, bufB, t, tid, true);   // L3: 256 -> 256

    // L4: 256 -> 1, per-atom warp reduction
    {
        int lane = tid & 31, wrp = tid >> 5;
        for (int a = wrp; a < na; a += 8) {
            float s = 0.0f;
            for (int f = lane; f < H; f += 32)
                s += bufB[a * H + f] * w4[t * H + f];
            #pragma unroll
            for (int o = 16; o; o >>= 1) s += __shfl_down_sync(0xFFFFFFFFu, s, o);
            if (lane == 0) {
                int gi = g_list[t * NATOMS + base + a];
                g_energy[gi] = s + b4[t];
            }
        }
    }
}

__global__ void k_reduce(float* __restrict__ out) {
    __shared__ float sh[256];
    float s = 0.0f;
    for (int i = threadIdx.x; i < NATOMS; i += 256) s += g_energy[i];
    sh[threadIdx.x] = s;
    __syncthreads();
    for (int o = 128; o; o >>= 1) {
        if (threadIdx.x < o) sh[threadIdx.x] += sh[threadIdx.x + o];
        __syncthreads();
    }
    if (threadIdx.x == 0) out[0] = sh[0];
}

// ---------------- launch ----------------
extern "C" void kernel_launch(void* const* d_in, const int* in_sizes, int n_in,
                              void* d_out, int out_size) {
    const float* xyz   = (const float*)d_in[0];
    const float* box   = (const float*)d_in[1];
    const int*   types = (const int*)  d_in[2];
    const float* w1 = (const float*)d_in[3];
    const float* b1 = (const float*)d_in[4];
    const float* w2 = (const float*)d_in[5];
    const float* b2 = (const float*)d_in[6];
    const float* w3 = (const float*)d_in[7];
    const float* b3 = (const float*)d_in[8];
    const float* w4 = (const float*)d_in[9];
    const float* b4 = (const float*)d_in[10];

    k_init  <<<1, 1>>>();
    k_lists <<<NATOMS / 256, 256>>>(types);
    k_desc  <<<NATOMS, 256>>>(xyz, box, types);
    k_mlp   <<<512, 256>>>(w1, b1, w2, b2, w3, b3, w4, b4);
    k_reduce<<<1, 256>>>((float*)d_out);
}